// round 2
// baseline (speedup 1.0000x reference)
#include <cuda_runtime.h>

#define TSEQ 512
#define INF  14
#define HID  8

typedef unsigned long long ull;

__device__ __forceinline__ ull pk(float lo, float hi){
    ull r; asm("mov.b64 %0, {%1,%2};" : "=l"(r) : "f"(lo), "f"(hi)); return r;
}
__device__ __forceinline__ float2 upk(ull v){
    float2 r; asm("mov.b64 {%0,%1}, %2;" : "=f"(r.x), "=f"(r.y) : "l"(v)); return r;
}
__device__ __forceinline__ ull ffma2(ull a, ull b, ull c){
    ull d; asm("fma.rn.f32x2 %0, %1, %2, %3;" : "=l"(d) : "l"(a), "l"(b), "l"(c)); return d;
}
__device__ __forceinline__ float rcpf(float x){
    float r; asm("rcp.approx.f32 %0, %1;" : "=f"(r) : "f"(x)); return r;
}
__device__ __forceinline__ float sigf(float x){
    // 1/(1+exp(-x)); exp overflow -> inf -> rcp -> 0 (correct limit)
    return rcpf(1.0f + __expf(-x));
}
__device__ __forceinline__ float tanh_f(float x){
    // 2/(1+exp(-2x)) - 1; correct at both infinities
    return fmaf(2.0f, rcpf(1.0f + __expf(-2.0f * x)), -1.0f);
}

__global__ __launch_bounds__(32, 1) void lstm_forex_kernel(
    const float* __restrict__ x,
    const float* __restrict__ Wih1, const float* __restrict__ Whh1,
    const float* __restrict__ bih1, const float* __restrict__ bhh1,
    const float* __restrict__ Wih2, const float* __restrict__ Whh2,
    const float* __restrict__ bih2, const float* __restrict__ bhh2,
    const float* __restrict__ bn_gamma, const float* __restrict__ bn_beta,
    const float* __restrict__ bn_mean, const float* __restrict__ bn_var,
    const float* __restrict__ w1, const float* __restrict__ b1,
    const float* __restrict__ w2, const float* __restrict__ b2,
    float* __restrict__ out, int Bn)
{
    __shared__ __align__(16) float sm[64];   // 4 groups x (h1[8], h2[8])

    const int lane = threadIdx.x & 31;
    const int j    = lane & 7;               // h-index this lane owns
    const int grp  = lane >> 3;              // element group within warp (0..3)
    const int e    = blockIdx.x * 4 + grp;
    const bool valid = (e < Bn);
    const int ec = valid ? e : (Bn > 0 ? Bn - 1 : 0);
    const unsigned FULL = 0xffffffffu;
    float* smh1 = &sm[grp * 16];             // h1 vector for this group
    float* smh2 = &sm[grp * 16 + 8];         // h2 vector

    // ---- pack per-lane weight rows (gates i,f,g,o = rows j, j+8, j+16, j+24) ----
    // k-parity packing: pair k holds (W[row][2k], W[row][2k+1])
    ull wxp[4][7], wh1p[4][4], wi2p[4][4], wh2p[4][4], pb1[4], pb2[4];
#pragma unroll
    for (int g = 0; g < 4; g++){
        const int row = g * 8 + j;
#pragma unroll
        for (int k = 0; k < 7; k++)
            wxp[g][k] = pk(Wih1[row * 14 + 2*k], Wih1[row * 14 + 2*k + 1]);
#pragma unroll
        for (int k = 0; k < 4; k++){
            wh1p[g][k] = pk(Whh1[row * 8 + 2*k], Whh1[row * 8 + 2*k + 1]);
            wi2p[g][k] = pk(Wih2[row * 8 + 2*k], Wih2[row * 8 + 2*k + 1]);
            wh2p[g][k] = pk(Whh2[row * 8 + 2*k], Whh2[row * 8 + 2*k + 1]);
        }
        pb1[g] = pk(bih1[row] + bhh1[row], 0.f);
        pb2[g] = pk(bih2[row] + bhh2[row], 0.f);
    }

    // zero h2 smem (read at t=0 before first h2 store); h1 smem written before first read
    smh2[j] = 0.f;

    // x[e, t, :] : 14 floats = 7 packed pairs, 8B-aligned
    const ull* px = reinterpret_cast<const ull*>(x) + (size_t)ec * (TSEQ * INF / 2);
    ull xb[7];
#pragma unroll
    for (int k = 0; k < 7; k++) xb[k] = px[k];
    px += 7;

    // h1 pairs held in registers (h1(t-1) packed as (h0,h1)(h2,h3)(h4,h5)(h6,h7))
    ull h1p[4] = {0ull, 0ull, 0ull, 0ull};
    ull h2p[4];
    float c1 = 0.f, c2 = 0.f, h2s = 0.f;

#pragma unroll 1
    for (int t = 0; t < TSEQ; t++){
        // ---------------- layer 1 ----------------
        ull acc0 = pb1[0], acc1 = pb1[1], acc2 = pb1[2], acc3 = pb1[3];
#pragma unroll
        for (int k = 0; k < 7; k++){
            acc0 = ffma2(wxp[0][k], xb[k], acc0);
            acc1 = ffma2(wxp[1][k], xb[k], acc1);
            acc2 = ffma2(wxp[2][k], xb[k], acc2);
            acc3 = ffma2(wxp[3][k], xb[k], acc3);
        }
        if (t + 1 < TSEQ){                    // prefetch next timestep's x
#pragma unroll
            for (int k = 0; k < 7; k++) xb[k] = px[k];
            px += 7;
        }
#pragma unroll
        for (int k = 0; k < 4; k++){
            acc0 = ffma2(wh1p[0][k], h1p[k], acc0);
            acc1 = ffma2(wh1p[1][k], h1p[k], acc1);
            acc2 = ffma2(wh1p[2][k], h1p[k], acc2);
            acc3 = ffma2(wh1p[3][k], h1p[k], acc3);
        }
        float h1s;
        {
            float2 u0 = upk(acc0), u1 = upk(acc1), u2 = upk(acc2), u3 = upk(acc3);
            const float ai = sigf(u0.x + u0.y);
            const float af = sigf(u1.x + u1.y);
            const float ag = tanh_f(u2.x + u2.y);
            const float ao = sigf(u3.x + u3.y);
            c1 = fmaf(af, c1, ai * ag);
            h1s = ao * tanh_f(c1);
        }
        smh1[j] = h1s;
        __syncwarp(FULL);
        {   // reload packed h1(t) and h2(t-1) pairs (LDS.128 x4)
            ulonglong2 va = *reinterpret_cast<const ulonglong2*>(smh1);
            ulonglong2 vb = *reinterpret_cast<const ulonglong2*>(smh1 + 4);
            h1p[0] = va.x; h1p[1] = va.y; h1p[2] = vb.x; h1p[3] = vb.y;
            ulonglong2 vc = *reinterpret_cast<const ulonglong2*>(smh2);
            ulonglong2 vd = *reinterpret_cast<const ulonglong2*>(smh2 + 4);
            h2p[0] = vc.x; h2p[1] = vc.y; h2p[2] = vd.x; h2p[3] = vd.y;
        }
        // ---------------- layer 2 ----------------
        acc0 = pb2[0]; acc1 = pb2[1]; acc2 = pb2[2]; acc3 = pb2[3];
#pragma unroll
        for (int k = 0; k < 4; k++){
            acc0 = ffma2(wi2p[0][k], h1p[k], acc0);
            acc1 = ffma2(wi2p[1][k], h1p[k], acc1);
            acc2 = ffma2(wi2p[2][k], h1p[k], acc2);
            acc3 = ffma2(wi2p[3][k], h1p[k], acc3);
        }
#pragma unroll
        for (int k = 0; k < 4; k++){
            acc0 = ffma2(wh2p[0][k], h2p[k], acc0);
            acc1 = ffma2(wh2p[1][k], h2p[k], acc1);
            acc2 = ffma2(wh2p[2][k], h2p[k], acc2);
            acc3 = ffma2(wh2p[3][k], h2p[k], acc3);
        }
        {
            float2 u0 = upk(acc0), u1 = upk(acc1), u2 = upk(acc2), u3 = upk(acc3);
            const float ai = sigf(u0.x + u0.y);
            const float af = sigf(u1.x + u1.y);
            const float ag = tanh_f(u2.x + u2.y);
            const float ao = sigf(u3.x + u3.y);
            c2 = fmaf(af, c2, ai * ag);
            h2s = ao * tanh_f(c2);
        }
        smh2[j] = h2s;
        // next iteration's __syncwarp covers this store before its LDS
    }

    // ---------------- epilogue: BatchNorm (eval) + MLP head ----------------
    const float scale = bn_gamma[j] * rsqrtf(bn_var[j] + 1e-5f);
    const float nrm   = fmaf(h2s - bn_mean[j], scale, bn_beta[j]);

    float p0 = w1[0 * 8 + j] * nrm;
    float p1 = w1[1 * 8 + j] * nrm;
    float p2 = w1[2 * 8 + j] * nrm;
    float p3 = w1[3 * 8 + j] * nrm;
#pragma unroll
    for (int off = 4; off > 0; off >>= 1){
        p0 += __shfl_xor_sync(FULL, p0, off);
        p1 += __shfl_xor_sync(FULL, p1, off);
        p2 += __shfl_xor_sync(FULL, p2, off);
        p3 += __shfl_xor_sync(FULL, p3, off);
    }
    if (valid && j == 0){
        float o = b2[0];
        o = fmaf(w2[0], fmaxf(p0 + b1[0], 0.f), o);
        o = fmaf(w2[1], fmaxf(p1 + b1[1], 0.f), o);
        o = fmaf(w2[2], fmaxf(p2 + b1[2], 0.f), o);
        o = fmaf(w2[3], fmaxf(p3 + b1[3], 0.f), o);
        out[e] = o;
    }
}

extern "C" void kernel_launch(void* const* d_in, const int* in_sizes, int n_in,
                              void* d_out, int out_size)
{
    const float* x        = (const float*)d_in[0];
    const float* Wih1     = (const float*)d_in[1];
    const float* Whh1     = (const float*)d_in[2];
    const float* bih1     = (const float*)d_in[3];
    const float* bhh1     = (const float*)d_in[4];
    const float* Wih2     = (const float*)d_in[5];
    const float* Whh2     = (const float*)d_in[6];
    const float* bih2     = (const float*)d_in[7];
    const float* bhh2     = (const float*)d_in[8];
    const float* bn_gamma = (const float*)d_in[9];
    const float* bn_beta  = (const float*)d_in[10];
    const float* bn_mean  = (const float*)d_in[11];
    const float* bn_var   = (const float*)d_in[12];
    const float* w1       = (const float*)d_in[13];
    const float* b1       = (const float*)d_in[14];
    const float* w2       = (const float*)d_in[15];
    const float* b2       = (const float*)d_in[16];

    const int Bn = in_sizes[0] / (TSEQ * INF);
    const int grid = (Bn + 3) / 4;           // 4 batch elements per warp, 1 warp per block

    lstm_forex_kernel<<<grid, 32>>>(x, Wih1, Whh1, bih1, bhh1,
                                    Wih2, Whh2, bih2, bhh2,
                                    bn_gamma, bn_beta, bn_mean, bn_var,
                                    w1, b1, w2, b2,
                                    (float*)d_out, Bn);
}

// round 3
// speedup vs baseline: 1.2673x; 1.2673x over previous
#include <cuda_runtime.h>

#define TSEQ 512
#define INF  14
#define HID  8

typedef unsigned long long ull;

__device__ __forceinline__ ull pk(float lo, float hi){
    ull r; asm("mov.b64 %0, {%1,%2};" : "=l"(r) : "f"(lo), "f"(hi)); return r;
}
__device__ __forceinline__ float2 upk(ull v){
    float2 r; asm("mov.b64 {%0,%1}, %2;" : "=f"(r.x), "=f"(r.y) : "l"(v)); return r;
}
__device__ __forceinline__ ull ffma2(ull a, ull b, ull c){
    ull d; asm("fma.rn.f32x2 %0, %1, %2, %3;" : "=l"(d) : "l"(a), "l"(b), "l"(c)); return d;
}
__device__ __forceinline__ float tanhx(float x){
    float r; asm("tanh.approx.f32 %0, %1;" : "=f"(r) : "f"(x)); return r;
}
__device__ __forceinline__ float sigx(float x){
    return fmaf(0.5f, tanhx(0.5f * x), 0.5f);
}

__global__ __launch_bounds__(32, 1) void lstm_forex_kernel(
    const float* __restrict__ x,
    const float* __restrict__ Wih1, const float* __restrict__ Whh1,
    const float* __restrict__ bih1, const float* __restrict__ bhh1,
    const float* __restrict__ Wih2, const float* __restrict__ Whh2,
    const float* __restrict__ bih2, const float* __restrict__ bhh2,
    const float* __restrict__ bn_gamma, const float* __restrict__ bn_beta,
    const float* __restrict__ bn_mean, const float* __restrict__ bn_var,
    const float* __restrict__ w1, const float* __restrict__ b1,
    const float* __restrict__ w2, const float* __restrict__ b2,
    float* __restrict__ out, int Bn)
{
    const int lane = threadIdx.x & 31;
    const int j    = lane & 7;          // h-index this lane owns
    const int base = lane & 24;         // base lane of this element's 8-lane group
    const int e    = blockIdx.x * 4 + (lane >> 3);
    const bool valid = (e < Bn);
    const int ec = valid ? e : (Bn > 0 ? Bn - 1 : 0);
    const unsigned FULL = 0xffffffffu;

    // ---- pack per-lane weight rows (gates i,f,g,o = rows j, j+8, j+16, j+24) ----
    ull wxp[4][7];    // (Wih1[row][2k], Wih1[row][2k+1])
    ull wh1p[4][4];   // (Whh1[row][2k], Whh1[row][2k+1])
    ull wl2p[4][8];   // (Wih2[row][k],  Whh2[row][k])  -- interleaved for L2
    ull pb1[4], pb2[4];
#pragma unroll
    for (int g = 0; g < 4; g++){
        const int row = g * 8 + j;
#pragma unroll
        for (int k = 0; k < 7; k++)
            wxp[g][k] = pk(Wih1[row * 14 + 2*k], Wih1[row * 14 + 2*k + 1]);
#pragma unroll
        for (int k = 0; k < 4; k++)
            wh1p[g][k] = pk(Whh1[row * 8 + 2*k], Whh1[row * 8 + 2*k + 1]);
#pragma unroll
        for (int k = 0; k < 8; k++)
            wl2p[g][k] = pk(Wih2[row * 8 + k], Whh2[row * 8 + k]);
        pb1[g] = pk(bih1[row] + bhh1[row], 0.f);
        pb2[g] = pk(bih2[row] + bhh2[row], 0.f);
    }

    // x[e, t, :] : 14 floats = 7 packed pairs, 8B-aligned
    const ull* px = reinterpret_cast<const ull*>(x) + (size_t)ec * (TSEQ * INF / 2);
    ull xb[7];
#pragma unroll
    for (int k = 0; k < 7; k++) xb[k] = px[k];
    px += 7;

    float h1 = 0.f, c1 = 0.f, h2 = 0.f, c2 = 0.f;

#pragma unroll 1
    for (int t = 0; t < TSEQ; t++){
        // ---------------- layer 1: x projection (packed) ----------------
        ull acc0 = pb1[0], acc1 = pb1[1], acc2 = pb1[2], acc3 = pb1[3];
#pragma unroll
        for (int k = 0; k < 7; k++){
            acc0 = ffma2(wxp[0][k], xb[k], acc0);
            acc1 = ffma2(wxp[1][k], xb[k], acc1);
            acc2 = ffma2(wxp[2][k], xb[k], acc2);
            acc3 = ffma2(wxp[3][k], xb[k], acc3);
        }
        if (t + 1 < TSEQ){                    // prefetch next timestep's x
#pragma unroll
            for (int k = 0; k < 7; k++) xb[k] = px[k];
            px += 7;
        }
        // ---------------- layer 1: recurrent dot (packed pairs of h1) ----------------
#pragma unroll
        for (int k = 0; k < 4; k++){
            const float ha = __shfl_sync(FULL, h1, base + 2*k);
            const float hb = __shfl_sync(FULL, h1, base + 2*k + 1);
            const ull hp = pk(ha, hb);
            acc0 = ffma2(wh1p[0][k], hp, acc0);
            acc1 = ffma2(wh1p[1][k], hp, acc1);
            acc2 = ffma2(wh1p[2][k], hp, acc2);
            acc3 = ffma2(wh1p[3][k], hp, acc3);
        }
        {
            float2 u0 = upk(acc0), u1 = upk(acc1), u2 = upk(acc2), u3 = upk(acc3);
            const float ai = sigx(u0.x + u0.y);
            const float af = sigx(u1.x + u1.y);
            const float ag = tanhx(u2.x + u2.y);
            const float ao = sigx(u3.x + u3.y);
            c1 = fmaf(af, c1, ai * ag);
            h1 = ao * tanhx(c1);
        }
        // ---------------- layer 2: (h1,h2) interleaved dot ----------------
        acc0 = pb2[0]; acc1 = pb2[1]; acc2 = pb2[2]; acc3 = pb2[3];
#pragma unroll
        for (int k = 0; k < 8; k++){
            const float h1k = __shfl_sync(FULL, h1, base + k);
            const float h2k = __shfl_sync(FULL, h2, base + k);
            const ull hp = pk(h1k, h2k);
            acc0 = ffma2(wl2p[0][k], hp, acc0);
            acc1 = ffma2(wl2p[1][k], hp, acc1);
            acc2 = ffma2(wl2p[2][k], hp, acc2);
            acc3 = ffma2(wl2p[3][k], hp, acc3);
        }
        {
            float2 u0 = upk(acc0), u1 = upk(acc1), u2 = upk(acc2), u3 = upk(acc3);
            const float ai = sigx(u0.x + u0.y);
            const float af = sigx(u1.x + u1.y);
            const float ag = tanhx(u2.x + u2.y);
            const float ao = sigx(u3.x + u3.y);
            c2 = fmaf(af, c2, ai * ag);
            h2 = ao * tanhx(c2);
        }
    }

    // ---------------- epilogue: BatchNorm (eval) + MLP head ----------------
    const float scale = bn_gamma[j] * rsqrtf(bn_var[j] + 1e-5f);
    const float nrm   = fmaf(h2 - bn_mean[j], scale, bn_beta[j]);

    float p0 = w1[0 * 8 + j] * nrm;
    float p1 = w1[1 * 8 + j] * nrm;
    float p2 = w1[2 * 8 + j] * nrm;
    float p3 = w1[3 * 8 + j] * nrm;
#pragma unroll
    for (int off = 4; off > 0; off >>= 1){
        p0 += __shfl_xor_sync(FULL, p0, off);
        p1 += __shfl_xor_sync(FULL, p1, off);
        p2 += __shfl_xor_sync(FULL, p2, off);
        p3 += __shfl_xor_sync(FULL, p3, off);
    }
    if (valid && j == 0){
        float o = b2[0];
        o = fmaf(w2[0], fmaxf(p0 + b1[0], 0.f), o);
        o = fmaf(w2[1], fmaxf(p1 + b1[1], 0.f), o);
        o = fmaf(w2[2], fmaxf(p2 + b1[2], 0.f), o);
        o = fmaf(w2[3], fmaxf(p3 + b1[3], 0.f), o);
        out[e] = o;
    }
}

extern "C" void kernel_launch(void* const* d_in, const int* in_sizes, int n_in,
                              void* d_out, int out_size)
{
    const float* x        = (const float*)d_in[0];
    const float* Wih1     = (const float*)d_in[1];
    const float* Whh1     = (const float*)d_in[2];
    const float* bih1     = (const float*)d_in[3];
    const float* bhh1     = (const float*)d_in[4];
    const float* Wih2     = (const float*)d_in[5];
    const float* Whh2     = (const float*)d_in[6];
    const float* bih2     = (const float*)d_in[7];
    const float* bhh2     = (const float*)d_in[8];
    const float* bn_gamma = (const float*)d_in[9];
    const float* bn_beta  = (const float*)d_in[10];
    const float* bn_mean  = (const float*)d_in[11];
    const float* bn_var   = (const float*)d_in[12];
    const float* w1       = (const float*)d_in[13];
    const float* b1       = (const float*)d_in[14];
    const float* w2       = (const float*)d_in[15];
    const float* b2       = (const float*)d_in[16];

    const int Bn = in_sizes[0] / (TSEQ * INF);
    const int grid = (Bn + 3) / 4;            // 4 batch elements per warp, 1 warp/block

    lstm_forex_kernel<<<grid, 32>>>(x, Wih1, Whh1, bih1, bhh1,
                                    Wih2, Whh2, bih2, bhh2,
                                    bn_gamma, bn_beta, bn_mean, bn_var,
                                    w1, b1, w2, b2,
                                    (float*)d_out, Bn);
}